// round 1
// baseline (speedup 1.0000x reference)
#include <cuda_runtime.h>

#define CH 512
#define NB 256
#define LOG2E 1.4426950408889634f

__device__ __forceinline__ float ex2(float x) {
    float r;
    asm("ex2.approx.ftz.f32 %0, %1;" : "=f"(r) : "f"(x));
    return r;
}

__global__ __launch_bounds__(256) void attn1d_kernel(
    const float* __restrict__ q, const float* __restrict__ k, const float* __restrict__ v,
    const float* __restrict__ wq, const float* __restrict__ wk, const float* __restrict__ wv,
    float* __restrict__ out)
{
    // padded rows: index i+2 holds element i; [0,1] and [CH+2, CH+3] are zero pad
    __shared__ float sq[CH + 4], sk[CH + 4], sv[CH + 4];
    __shared__ float2 skv[CH];       // {kh * log2e, vh}
    __shared__ float red[16];        // [0..7] warp maxes, [8..15] warp mins

    const int b = blockIdx.x;
    const int t = threadIdx.x;

    const float* qb = q + b * CH;
    const float* kb = k + b * CH;
    const float* vb = v + b * CH;

    if (t < 4) {
        const int i = (t < 2) ? t : (CH + t);  // 0,1,CH+2,CH+3
        sq[i] = 0.f; sk[i] = 0.f; sv[i] = 0.f;
    }
    sq[t + 2]   = qb[t];
    sq[t + 258] = qb[t + 256];
    sk[t + 2]   = kb[t];
    sk[t + 258] = kb[t + 256];
    sv[t + 2]   = vb[t];
    sv[t + 258] = vb[t + 256];

    float Wq[5], Wk[5], Wv[5];
    #pragma unroll
    for (int j = 0; j < 5; j++) { Wq[j] = wq[j]; Wk[j] = wk[j]; Wv[j] = wv[j]; }

    __syncthreads();

    // K=5 "same" cross-correlation for q, k, v at c = t and c = t+256
    float lmax = -1e30f, lmin = 1e30f;
    float s0 = 0.f, s1 = 0.f;
    #pragma unroll
    for (int h = 0; h < 2; h++) {
        const int c = t + h * 256;
        float kh = 0.f, vh = 0.f, qh = 0.f;
        #pragma unroll
        for (int j = 0; j < 5; j++) {
            kh = fmaf(Wk[j], sk[c + j], kh);
            vh = fmaf(Wv[j], sv[c + j], vh);
            qh = fmaf(Wq[j], sq[c + j], qh);
        }
        const float khL = kh * LOG2E;
        skv[c] = make_float2(khL, vh);
        lmax = fmaxf(lmax, khL);
        lmin = fminf(lmin, khL);
        if (h == 0) s0 = qh; else s1 = qh;
    }

    // block reduce kh max/min (in log2e-scaled domain; scaling is positive so order preserved)
    #pragma unroll
    for (int o = 16; o; o >>= 1) {
        lmax = fmaxf(lmax, __shfl_xor_sync(0xffffffffu, lmax, o));
        lmin = fminf(lmin, __shfl_xor_sync(0xffffffffu, lmin, o));
    }
    if ((t & 31) == 0) { red[t >> 5] = lmax; red[8 + (t >> 5)] = lmin; }
    __syncthreads();
    float kmax = red[0], kmin = red[8];
    #pragma unroll
    for (int i = 1; i < 8; i++) {
        kmax = fmaxf(kmax, red[i]);
        kmin = fminf(kmin, red[8 + i]);
    }

    // per-channel stable softmax-weighted sum (scores = s * kh_d, rank-1)
    const float m0 = fmaxf(s0 * kmax, s0 * kmin);
    const float m1 = fmaxf(s1 * kmax, s1 * kmin);
    float num0 = 0.f, den0 = 0.f, num1 = 0.f, den1 = 0.f;

    #pragma unroll 8
    for (int d = 0; d < CH; d++) {
        const float2 p = skv[d];           // broadcast LDS.64
        const float e0 = ex2(fmaf(s0, p.x, -m0));
        const float e1 = ex2(fmaf(s1, p.x, -m1));
        num0 = fmaf(e0, p.y, num0); den0 += e0;
        num1 = fmaf(e1, p.y, num1); den1 += e1;
    }

    out[b * CH + t]       = num0 / den0;
    out[b * CH + t + 256] = num1 / den1;
}

extern "C" void kernel_launch(void* const* d_in, const int* in_sizes, int n_in,
                              void* d_out, int out_size) {
    const float* q  = (const float*)d_in[0];
    const float* k  = (const float*)d_in[1];
    const float* v  = (const float*)d_in[2];
    const float* wq = (const float*)d_in[3];
    const float* wk = (const float*)d_in[4];
    const float* wv = (const float*)d_in[5];
    float* out = (float*)d_out;
    attn1d_kernel<<<NB, 256>>>(q, k, v, wq, wk, wv, out);
}